// round 1
// baseline (speedup 1.0000x reference)
#include <cuda_runtime.h>
#include <cstdint>

// ---------------------------------------------------------------------------
// Problem constants
//   rgb/depth: (B=8, C=64, H=64, W=192) fp32
//   corr:      (8, 20(di), 20(dj), 64, 192)
//   block1 s1: dw 3x3x3 (C=20,D=20,H=64,W=192) -> pw 20->20
//   block2 s2: dw -> (20,10,32,96)             -> pw 20->40
//   block3 s1: dw (C=40,D=10,H=32,W=96)        -> pw 40->40
//   block4 s2: dw -> (40,5,16,48)              -> pw 40->80  (output)
// ---------------------------------------------------------------------------

#define NB   8
#define NC   64
#define NH   64
#define NW   192
#define NP   20

// ping-pong scratch (39,321,600 floats each = 157 MB, .bss — allowed)
__device__ float g_bufA[NB * NP * NP * NH * NW];
__device__ float g_bufB[NB * NP * NP * NH * NW];

__device__ __forceinline__ float leaky(float x) {
    return x > 0.0f ? x : 0.1f * x;
}

// ---------------------------------------------------------------------------
// Correlation kernel: block = (h, b). smem: rgb row [64][192], depth row [64][212]
// thread tile: 8 w  x 4 dj  (120 active work items, 128 threads)
// ---------------------------------------------------------------------------
__global__ void corr_kernel(const float* __restrict__ rgb,
                            const float* __restrict__ dep,
                            float* __restrict__ out)
{
    const int h = blockIdx.x;
    const int b = blockIdx.y;
    const int tid = threadIdx.x;

    extern __shared__ float sm[];
    float* sm_rgb = sm;               // 64*192
    float* sm_dep = sm + 64 * 192;    // 64*212   (x = w + dj, x in [0,211))

    const float* rgbb = rgb + (size_t)b * NC * NH * NW;
    const float* depb = dep + (size_t)b * NC * NH * NW;

    // load rgb row once: 64 channels x 192 w  (3072 float4)
    for (int i = tid; i < 64 * 48; i += blockDim.x) {
        int c = i / 48;
        int w4 = (i - c * 48) * 4;
        *(float4*)&sm_rgb[c * 192 + w4] =
            *(const float4*)&rgbb[(size_t)c * (NH * NW) + h * NW + w4];
    }

    const int item = tid;                 // 0..119 active
    const bool active = (item < 120);
    const int wg  = item % 24;
    const int djg = item / 24;
    const int w0  = wg * 8;
    const int dj0 = djg * 4;
    const int x0  = w0 + dj0;             // 4-aligned

    for (int di = 0; di < NP; di++) {
        __syncthreads();   // previous compute done before overwrite
        const int hr = h + di - 10;
        if (hr >= 0 && hr < NH) {
            for (int i = tid; i < 64 * 212; i += blockDim.x) {
                int c = i / 212;
                int x = i - c * 212;
                int xr = x - 10;
                float v = 0.0f;
                if (xr >= 0 && xr < NW)
                    v = depb[(size_t)c * (NH * NW) + hr * NW + xr];
                sm_dep[i] = v;
            }
        } else {
            for (int i = tid; i < 64 * 212; i += blockDim.x) sm_dep[i] = 0.0f;
        }
        __syncthreads();
        if (!active) continue;

        float acc[4][8];
        #pragma unroll
        for (int j = 0; j < 4; j++)
            #pragma unroll
            for (int i = 0; i < 8; i++) acc[j][i] = 0.0f;

        #pragma unroll 4
        for (int c = 0; c < 64; c++) {
            float4 r0 = *(const float4*)&sm_rgb[c * 192 + w0];
            float4 r1 = *(const float4*)&sm_rgb[c * 192 + w0 + 4];
            float4 d0 = *(const float4*)&sm_dep[c * 212 + x0];
            float4 d1 = *(const float4*)&sm_dep[c * 212 + x0 + 4];
            float4 d2 = *(const float4*)&sm_dep[c * 212 + x0 + 8];
            float r[8]  = {r0.x, r0.y, r0.z, r0.w, r1.x, r1.y, r1.z, r1.w};
            float dv[12] = {d0.x, d0.y, d0.z, d0.w,
                            d1.x, d1.y, d1.z, d1.w,
                            d2.x, d2.y, d2.z, d2.w};
            #pragma unroll
            for (int j = 0; j < 4; j++)
                #pragma unroll
                for (int i = 0; i < 8; i++)
                    acc[j][i] += r[i] * dv[i + j];
        }

        #pragma unroll
        for (int j = 0; j < 4; j++) {
            size_t base = ((((size_t)b * NP + di) * NP + (dj0 + j)) * NH + h) * NW + w0;
            float4 o0 = {acc[j][0], acc[j][1], acc[j][2], acc[j][3]};
            float4 o1 = {acc[j][4], acc[j][5], acc[j][6], acc[j][7]};
            *(float4*)&out[base]     = o0;
            *(float4*)&out[base + 4] = o1;
        }
    }
}

// ---------------------------------------------------------------------------
// Depthwise 3x3x3, stride 1, pad 1, + leaky.
// block = (n, c, d, h-tile of 16). smem: 3 z-planes x 18 rows x (W+4)
// ---------------------------------------------------------------------------
__global__ void dw_s1_kernel(const float* __restrict__ in,
                             const float* __restrict__ wgt,
                             const float* __restrict__ bias,
                             float* __restrict__ out,
                             int C, int D, int H, int W, int htiles)
{
    __shared__ float smp[3 * 18 * 196];   // max: W=192 -> SW=196

    int bx = blockIdx.x;
    const int ht = bx % htiles;  bx /= htiles;
    const int d  = bx % D;       bx /= D;
    const int c  = bx % C;
    const int n  = bx / C;
    const int h0 = ht * 16;
    const int SW = W + 4;                 // keeps float4 loads aligned
    const int tid = threadIdx.x;

    const float* inb = in + (size_t)(n * C + c) * D * H * W;

    const int total = 3 * 18 * SW;
    for (int i = tid; i < total; i += blockDim.x) {
        int z = i / (18 * SW);
        int r = i - z * 18 * SW;
        int y = r / SW;
        int x = r - y * SW;
        int zi = d - 1 + z, yi = h0 - 1 + y, xi = x - 1;
        float v = 0.0f;
        if (zi >= 0 && zi < D && yi >= 0 && yi < H && xi >= 0 && xi < W)
            v = inb[(size_t)zi * H * W + yi * W + xi];
        smp[i] = v;
    }

    float wt[27];
    #pragma unroll
    for (int k = 0; k < 27; k++) wt[k] = __ldg(&wgt[c * 27 + k]);
    const float bb = __ldg(&bias[c]);
    __syncthreads();

    const int wq = W / 4;
    const int items = 16 * wq;
    for (int it = tid; it < items; it += blockDim.x) {
        int hl  = it / wq;
        int wg4 = (it - hl * wq) * 4;
        float a0 = bb, a1 = bb, a2 = bb, a3 = bb;
        #pragma unroll
        for (int z = 0; z < 3; z++)
            #pragma unroll
            for (int y = 0; y < 3; y++) {
                const float* row = &smp[(z * 18 + hl + y) * SW + wg4];
                float4 v4 = *(const float4*)row;
                float v4a = row[4];
                float v5  = row[5];
                float w0 = wt[(z * 3 + y) * 3 + 0];
                float w1 = wt[(z * 3 + y) * 3 + 1];
                float w2 = wt[(z * 3 + y) * 3 + 2];
                a0 += w0 * v4.x + w1 * v4.y + w2 * v4.z;
                a1 += w0 * v4.y + w1 * v4.z + w2 * v4.w;
                a2 += w0 * v4.z + w1 * v4.w + w2 * v4a;
                a3 += w0 * v4.w + w1 * v4a  + w2 * v5;
            }
        float4 o = {leaky(a0), leaky(a1), leaky(a2), leaky(a3)};
        *(float4*)&out[((size_t)(n * C + c) * D + d) * H * W + (h0 + hl) * W + wg4] = o;
    }
}

// ---------------------------------------------------------------------------
// Depthwise 3x3x3, stride 2, pad 1, + leaky. One thread per output (small layers).
// ---------------------------------------------------------------------------
__global__ void dw_s2_kernel(const float* __restrict__ in,
                             const float* __restrict__ wgt,
                             const float* __restrict__ bias,
                             float* __restrict__ out,
                             int C, int D, int H, int W,
                             int Do, int Ho, int Wo, int total)
{
    int idx = blockIdx.x * blockDim.x + threadIdx.x;
    if (idx >= total) return;
    int t = idx;
    const int wo = t % Wo; t /= Wo;
    const int ho = t % Ho; t /= Ho;
    const int dd = t % Do; t /= Do;
    const int c  = t % C;
    const int n  = t / C;

    const float* inb = in + (size_t)(n * C + c) * D * H * W;
    const float* wp  = &wgt[c * 27];
    float acc = __ldg(&bias[c]);
    #pragma unroll
    for (int kz = 0; kz < 3; kz++) {
        int zi = 2 * dd - 1 + kz;
        if (zi < 0 || zi >= D) continue;
        #pragma unroll
        for (int ky = 0; ky < 3; ky++) {
            int yi = 2 * ho - 1 + ky;
            if (yi < 0 || yi >= H) continue;
            #pragma unroll
            for (int kx = 0; kx < 3; kx++) {
                int xi = 2 * wo - 1 + kx;
                if (xi < 0 || xi >= W) continue;
                acc += __ldg(&wp[(kz * 3 + ky) * 3 + kx]) *
                       __ldg(&inb[(size_t)zi * H * W + yi * W + xi]);
            }
        }
    }
    out[idx] = leaky(acc);   // idx is linear over (n,c,do,ho,wo)
}

// ---------------------------------------------------------------------------
// Pointwise Cin->Cout + leaky. Thread = 4 contiguous positions x 10-co tile.
// grid.y = Cout/10. plane (=D*H*W) is a multiple of 4 for all layers.
// ---------------------------------------------------------------------------
__global__ void pw_kernel(const float* __restrict__ in,
                          const float* __restrict__ wgt,
                          const float* __restrict__ bias,
                          float* __restrict__ out,
                          int Cin, int Cout, int plane, int nquad)
{
    __shared__ float sw[10 * 40];
    __shared__ float sb[10];

    const int co0 = blockIdx.y * 10;
    const int tid = threadIdx.x;

    for (int i = tid; i < 10 * Cin; i += blockDim.x) {
        int j  = i / Cin;
        int ci = i - j * Cin;
        sw[i] = wgt[(co0 + j) * Cin + ci];
    }
    if (tid < 10) sb[tid] = bias[co0 + tid];
    __syncthreads();

    const int t = blockIdx.x * blockDim.x + tid;
    if (t >= nquad) return;
    const int s0 = t * 4;
    const int n  = s0 / plane;
    const int p  = s0 - n * plane;

    const float* inb = in + (size_t)n * Cin * plane + p;

    float acc[10][4];
    #pragma unroll
    for (int j = 0; j < 10; j++) {
        float bv = sb[j];
        acc[j][0] = bv; acc[j][1] = bv; acc[j][2] = bv; acc[j][3] = bv;
    }

    #pragma unroll 4
    for (int ci = 0; ci < Cin; ci++) {
        float4 x4 = *(const float4*)&inb[(size_t)ci * plane];
        #pragma unroll
        for (int j = 0; j < 10; j++) {
            float wv = sw[j * Cin + ci];
            acc[j][0] += wv * x4.x;
            acc[j][1] += wv * x4.y;
            acc[j][2] += wv * x4.z;
            acc[j][3] += wv * x4.w;
        }
    }

    float* ob = out + (size_t)n * Cout * plane + p;
    #pragma unroll
    for (int j = 0; j < 10; j++) {
        float4 o = {leaky(acc[j][0]), leaky(acc[j][1]),
                    leaky(acc[j][2]), leaky(acc[j][3])};
        *(float4*)&ob[(size_t)(co0 + j) * plane] = o;
    }
}

// ---------------------------------------------------------------------------
extern "C" void kernel_launch(void* const* d_in, const int* in_sizes, int n_in,
                              void* d_out, int out_size)
{
    const float* rgb   = (const float*)d_in[0];
    const float* dep   = (const float*)d_in[1];
    const float* dw1_w = (const float*)d_in[2];
    const float* dw1_b = (const float*)d_in[3];
    const float* pw1_w = (const float*)d_in[4];
    const float* pw1_b = (const float*)d_in[5];
    const float* dw2_w = (const float*)d_in[6];
    const float* dw2_b = (const float*)d_in[7];
    const float* pw2_w = (const float*)d_in[8];
    const float* pw2_b = (const float*)d_in[9];
    const float* dw3_w = (const float*)d_in[10];
    const float* dw3_b = (const float*)d_in[11];
    const float* pw3_w = (const float*)d_in[12];
    const float* pw3_b = (const float*)d_in[13];
    const float* dw4_w = (const float*)d_in[14];
    const float* dw4_b = (const float*)d_in[15];
    const float* pw4_w = (const float*)d_in[16];
    const float* pw4_b = (const float*)d_in[17];
    float* out = (float*)d_out;

    float *bufA = nullptr, *bufB = nullptr;
    cudaGetSymbolAddress((void**)&bufA, g_bufA);
    cudaGetSymbolAddress((void**)&bufB, g_bufB);

    // ---- correlation -> bufA ----
    const int smem_corr = (64 * 192 + 64 * 212) * 4;   // 103,424 B
    cudaFuncSetAttribute(corr_kernel,
                         cudaFuncAttributeMaxDynamicSharedMemorySize, smem_corr);
    corr_kernel<<<dim3(NH, NB), 128, smem_corr>>>(rgb, dep, bufA);

    // ---- block 1 (stride 1): dw 20ch on (20,64,192), pw 20->20 ----
    dw_s1_kernel<<<NB * 20 * 20 * 4, 256>>>(bufA, dw1_w, dw1_b, bufB,
                                            20, 20, 64, 192, 4);
    {
        const int plane = 20 * 64 * 192;           // 245,760
        const int nquad = NB * plane / 4;          // 491,520
        pw_kernel<<<dim3((nquad + 255) / 256, 2), 256>>>(bufB, pw1_w, pw1_b, bufA,
                                                         20, 20, plane, nquad);
    }

    // ---- block 2 (stride 2): dw -> (20,10,32,96), pw 20->40 ----
    {
        const int total = NB * 20 * 10 * 32 * 96;  // 4,915,200
        dw_s2_kernel<<<(total + 255) / 256, 256>>>(bufA, dw2_w, dw2_b, bufB,
                                                   20, 20, 64, 192,
                                                   10, 32, 96, total);
        const int plane = 10 * 32 * 96;            // 30,720
        const int nquad = NB * plane / 4;          // 61,440
        pw_kernel<<<dim3((nquad + 255) / 256, 4), 256>>>(bufB, pw2_w, pw2_b, bufA,
                                                         20, 40, plane, nquad);
    }

    // ---- block 3 (stride 1): dw 40ch on (10,32,96), pw 40->40 ----
    dw_s1_kernel<<<NB * 40 * 10 * 2, 256>>>(bufA, dw3_w, dw3_b, bufB,
                                            40, 10, 32, 96, 2);
    {
        const int plane = 10 * 32 * 96;
        const int nquad = NB * plane / 4;
        pw_kernel<<<dim3((nquad + 255) / 256, 4), 256>>>(bufB, pw3_w, pw3_b, bufA,
                                                         40, 40, plane, nquad);
    }

    // ---- block 4 (stride 2): dw -> (40,5,16,48), pw 40->80 -> d_out ----
    {
        const int total = NB * 40 * 5 * 16 * 48;   // 1,228,800
        dw_s2_kernel<<<(total + 255) / 256, 256>>>(bufA, dw4_w, dw4_b, bufB,
                                                   40, 10, 32, 96,
                                                   5, 16, 48, total);
        const int plane = 5 * 16 * 48;             // 3,840
        const int nquad = NB * plane / 4;          // 7,680
        pw_kernel<<<dim3((nquad + 255) / 256, 8), 256>>>(bufB, pw4_w, pw4_b, out,
                                                         40, 80, plane, nquad);
    }
}

// round 2
// speedup vs baseline: 1.4111x; 1.4111x over previous
#include <cuda_runtime.h>
#include <cstdint>

#define NB   8
#define NC   64
#define NH   64
#define NW   192
#define NP   20

// ping-pong scratch (157 MB each, .bss — allowed)
__device__ float g_bufA[NB * NP * NP * NH * NW];
__device__ float g_bufB[NB * NP * NP * NH * NW];

__device__ __forceinline__ float leaky(float x) {
    return x > 0.0f ? x : 0.1f * x;
}

// ---------------------------------------------------------------------------
// Correlation: block = (h, di, b). smem: rgb row [64][192] + depth row [64][212].
// 128 threads, thread tile 8w x 4dj (120 active). Loaded ONCE per block.
// ---------------------------------------------------------------------------
__global__ void __launch_bounds__(128, 2)
corr_kernel(const float* __restrict__ rgb,
            const float* __restrict__ dep,
            float* __restrict__ out)
{
    const int h  = blockIdx.x;
    const int di = blockIdx.y;
    const int b  = blockIdx.z;
    const int tid = threadIdx.x;

    extern __shared__ float sm[];
    float* sm_rgb = sm;               // 64*192
    float* sm_dep = sm + 64 * 192;    // 64*212  (x = w + dj)

    const float* rgbb = rgb + (size_t)b * NC * NH * NW;
    const float* depb = dep + (size_t)b * NC * NH * NW;

    // rgb row: 64 ch x 192 w (float4)
    for (int i = tid; i < 64 * 48; i += 128) {
        int c = i / 48;
        int w4 = (i - c * 48) * 4;
        *(float4*)&sm_rgb[c * 192 + w4] =
            *(const float4*)&rgbb[(size_t)c * (NH * NW) + h * NW + w4];
    }

    // depth row hr = h + di - 10, padded to x in [0,212)
    const int hr = h + di - 10;
    if (hr >= 0 && hr < NH) {
        for (int i = tid; i < 64 * 212; i += 128) {
            int c = i / 212;
            int x = i - c * 212;
            int xr = x - 10;
            float v = 0.0f;
            if (xr >= 0 && xr < NW)
                v = depb[(size_t)c * (NH * NW) + hr * NW + xr];
            sm_dep[i] = v;
        }
    } else {
        for (int i = tid; i < 64 * 212; i += 128) sm_dep[i] = 0.0f;
    }
    __syncthreads();

    if (tid >= 120) return;
    const int wg  = tid % 24;
    const int djg = tid / 24;
    const int w0  = wg * 8;
    const int dj0 = djg * 4;
    const int x0  = w0 + dj0;          // 4-aligned

    float acc[4][8];
    #pragma unroll
    for (int j = 0; j < 4; j++)
        #pragma unroll
        for (int i = 0; i < 8; i++) acc[j][i] = 0.0f;

    #pragma unroll 4
    for (int c = 0; c < 64; c++) {
        float4 r0 = *(const float4*)&sm_rgb[c * 192 + w0];
        float4 r1 = *(const float4*)&sm_rgb[c * 192 + w0 + 4];
        float4 d0 = *(const float4*)&sm_dep[c * 212 + x0];
        float4 d1 = *(const float4*)&sm_dep[c * 212 + x0 + 4];
        float4 d2 = *(const float4*)&sm_dep[c * 212 + x0 + 8];
        float r[8]   = {r0.x, r0.y, r0.z, r0.w, r1.x, r1.y, r1.z, r1.w};
        float dv[12] = {d0.x, d0.y, d0.z, d0.w,
                        d1.x, d1.y, d1.z, d1.w,
                        d2.x, d2.y, d2.z, d2.w};
        #pragma unroll
        for (int j = 0; j < 4; j++)
            #pragma unroll
            for (int i = 0; i < 8; i++)
                acc[j][i] += r[i] * dv[i + j];
    }

    #pragma unroll
    for (int j = 0; j < 4; j++) {
        size_t base = ((((size_t)b * NP + di) * NP + (dj0 + j)) * NH + h) * NW + w0;
        float4 o0 = {acc[j][0], acc[j][1], acc[j][2], acc[j][3]};
        float4 o1 = {acc[j][4], acc[j][5], acc[j][6], acc[j][7]};
        *(float4*)&out[base]     = o0;
        *(float4*)&out[base + 4] = o1;
    }
}

// ---------------------------------------------------------------------------
// Depthwise 3x3x3, stride 1, pad 1, + leaky. All dims constexpr.
// block = (n, c, d, h-tile of 16). smem: 3 z-planes x 18 rows x (W+4)
// ---------------------------------------------------------------------------
template<int C, int D, int H, int W, int HT>
__global__ void dw_s1_kernel(const float* __restrict__ in,
                             const float* __restrict__ wgt,
                             const float* __restrict__ bias,
                             float* __restrict__ out)
{
    constexpr int SW = W + 4;
    __shared__ float smp[3 * 18 * SW];

    int bx = blockIdx.x;
    const int ht = bx % HT;  bx /= HT;
    const int d  = bx % D;   bx /= D;
    const int c  = bx % C;
    const int n  = bx / C;
    const int h0 = ht * 16;
    const int tid = threadIdx.x;

    const float* inb = in + (size_t)(n * C + c) * D * H * W;

    constexpr int total = 3 * 18 * SW;
    for (int i = tid; i < total; i += blockDim.x) {
        int z = i / (18 * SW);
        int r = i - z * 18 * SW;
        int y = r / SW;
        int x = r - y * SW;
        int zi = d - 1 + z, yi = h0 - 1 + y, xi = x - 1;
        float v = 0.0f;
        if (zi >= 0 && zi < D && yi >= 0 && yi < H && xi >= 0 && xi < W)
            v = inb[(size_t)zi * H * W + yi * W + xi];
        smp[i] = v;
    }

    float wt[27];
    #pragma unroll
    for (int k = 0; k < 27; k++) wt[k] = __ldg(&wgt[c * 27 + k]);
    const float bb = __ldg(&bias[c]);
    __syncthreads();

    constexpr int wq = W / 4;
    constexpr int items = 16 * wq;
    for (int it = tid; it < items; it += blockDim.x) {
        int hl  = it / wq;
        int wg4 = (it - hl * wq) * 4;
        float a0 = bb, a1 = bb, a2 = bb, a3 = bb;
        #pragma unroll
        for (int z = 0; z < 3; z++)
            #pragma unroll
            for (int y = 0; y < 3; y++) {
                const float* row = &smp[(z * 18 + hl + y) * SW + wg4];
                float4 v4 = *(const float4*)row;
                float v4a = row[4];
                float v5  = row[5];
                float w0 = wt[(z * 3 + y) * 3 + 0];
                float w1 = wt[(z * 3 + y) * 3 + 1];
                float w2 = wt[(z * 3 + y) * 3 + 2];
                a0 += w0 * v4.x + w1 * v4.y + w2 * v4.z;
                a1 += w0 * v4.y + w1 * v4.z + w2 * v4.w;
                a2 += w0 * v4.z + w1 * v4.w + w2 * v4a;
                a3 += w0 * v4.w + w1 * v4a  + w2 * v5;
            }
        float4 o = {leaky(a0), leaky(a1), leaky(a2), leaky(a3)};
        *(float4*)&out[((size_t)(n * C + c) * D + d) * H * W + (h0 + hl) * W + wg4] = o;
    }
}

// ---------------------------------------------------------------------------
// Depthwise 3x3x3, stride 2, pad 1, + leaky. Dims constexpr, 1 thread/output.
// ---------------------------------------------------------------------------
template<int C, int D, int H, int W, int Do, int Ho, int Wo>
__global__ void dw_s2_kernel(const float* __restrict__ in,
                             const float* __restrict__ wgt,
                             const float* __restrict__ bias,
                             float* __restrict__ out)
{
    constexpr int total = NB * C * Do * Ho * Wo;
    int idx = blockIdx.x * blockDim.x + threadIdx.x;
    if (idx >= total) return;
    int t = idx;
    const int wo = t % Wo; t /= Wo;
    const int ho = t % Ho; t /= Ho;
    const int dd = t % Do; t /= Do;
    const int c  = t % C;
    const int n  = t / C;

    const float* inb = in + (size_t)(n * C + c) * D * H * W;
    const float* wp  = &wgt[c * 27];
    float acc = __ldg(&bias[c]);
    #pragma unroll
    for (int kz = 0; kz < 3; kz++) {
        int zi = 2 * dd - 1 + kz;
        if (zi < 0 || zi >= D) continue;
        #pragma unroll
        for (int ky = 0; ky < 3; ky++) {
            int yi = 2 * ho - 1 + ky;
            if (yi < 0 || yi >= H) continue;
            #pragma unroll
            for (int kx = 0; kx < 3; kx++) {
                int xi = 2 * wo - 1 + kx;
                if (xi < 0 || xi >= W) continue;
                acc += __ldg(&wp[(kz * 3 + ky) * 3 + kx]) *
                       __ldg(&inb[(size_t)zi * H * W + yi * W + xi]);
            }
        }
    }
    out[idx] = leaky(acc);
}

// ---------------------------------------------------------------------------
// Pointwise Cin->Cout + leaky. Thread = 4 contiguous positions x 10-co tile.
// ---------------------------------------------------------------------------
template<int Cin>
__global__ void pw_kernel(const float* __restrict__ in,
                          const float* __restrict__ wgt,
                          const float* __restrict__ bias,
                          float* __restrict__ out,
                          int Cout, int plane, int nquad)
{
    __shared__ float sw[10 * Cin];
    __shared__ float sb[10];

    const int co0 = blockIdx.y * 10;
    const int tid = threadIdx.x;

    for (int i = tid; i < 10 * Cin; i += blockDim.x) {
        int j  = i / Cin;
        int ci = i - j * Cin;
        sw[i] = wgt[(co0 + j) * Cin + ci];
    }
    if (tid < 10) sb[tid] = bias[co0 + tid];
    __syncthreads();

    const int t = blockIdx.x * blockDim.x + tid;
    if (t >= nquad) return;
    const int s0 = t * 4;
    const int n  = s0 / plane;
    const int p  = s0 - n * plane;

    const float* inb = in + (size_t)n * Cin * plane + p;

    float acc[10][4];
    #pragma unroll
    for (int j = 0; j < 10; j++) {
        float bv = sb[j];
        acc[j][0] = bv; acc[j][1] = bv; acc[j][2] = bv; acc[j][3] = bv;
    }

    #pragma unroll
    for (int ci = 0; ci < Cin; ci++) {
        float4 x4 = *(const float4*)&inb[(size_t)ci * plane];
        #pragma unroll
        for (int j = 0; j < 10; j++) {
            float wv = sw[j * Cin + ci];
            acc[j][0] += wv * x4.x;
            acc[j][1] += wv * x4.y;
            acc[j][2] += wv * x4.z;
            acc[j][3] += wv * x4.w;
        }
    }

    float* ob = out + (size_t)n * Cout * plane + p;
    #pragma unroll
    for (int j = 0; j < 10; j++) {
        float4 o = {leaky(acc[j][0]), leaky(acc[j][1]),
                    leaky(acc[j][2]), leaky(acc[j][3])};
        *(float4*)&ob[(size_t)(co0 + j) * plane] = o;
    }
}

// ---------------------------------------------------------------------------
extern "C" void kernel_launch(void* const* d_in, const int* in_sizes, int n_in,
                              void* d_out, int out_size)
{
    const float* rgb   = (const float*)d_in[0];
    const float* dep   = (const float*)d_in[1];
    const float* dw1_w = (const float*)d_in[2];
    const float* dw1_b = (const float*)d_in[3];
    const float* pw1_w = (const float*)d_in[4];
    const float* pw1_b = (const float*)d_in[5];
    const float* dw2_w = (const float*)d_in[6];
    const float* dw2_b = (const float*)d_in[7];
    const float* pw2_w = (const float*)d_in[8];
    const float* pw2_b = (const float*)d_in[9];
    const float* dw3_w = (const float*)d_in[10];
    const float* dw3_b = (const float*)d_in[11];
    const float* pw3_w = (const float*)d_in[12];
    const float* pw3_b = (const float*)d_in[13];
    const float* dw4_w = (const float*)d_in[14];
    const float* dw4_b = (const float*)d_in[15];
    const float* pw4_w = (const float*)d_in[16];
    const float* pw4_b = (const float*)d_in[17];
    float* out = (float*)d_out;

    float *bufA = nullptr, *bufB = nullptr;
    cudaGetSymbolAddress((void**)&bufA, g_bufA);
    cudaGetSymbolAddress((void**)&bufB, g_bufB);

    // ---- correlation -> bufA ----
    const int smem_corr = (64 * 192 + 64 * 212) * 4;   // 103,424 B
    cudaFuncSetAttribute(corr_kernel,
                         cudaFuncAttributeMaxDynamicSharedMemorySize, smem_corr);
    corr_kernel<<<dim3(NH, NP, NB), 128, smem_corr>>>(rgb, dep, bufA);

    // ---- block 1 (stride 1): dw 20ch on (20,64,192), pw 20->20 ----
    dw_s1_kernel<20, 20, 64, 192, 4><<<NB * 20 * 20 * 4, 256>>>(bufA, dw1_w, dw1_b, bufB);
    {
        const int plane = 20 * 64 * 192;
        const int nquad = NB * plane / 4;
        pw_kernel<20><<<dim3((nquad + 255) / 256, 2), 256>>>(bufB, pw1_w, pw1_b, bufA,
                                                             20, plane, nquad);
    }

    // ---- block 2 (stride 2): dw -> (20,10,32,96), pw 20->40 ----
    {
        const int total = NB * 20 * 10 * 32 * 96;
        dw_s2_kernel<20, 20, 64, 192, 10, 32, 96>
            <<<(total + 255) / 256, 256>>>(bufA, dw2_w, dw2_b, bufB);
        const int plane = 10 * 32 * 96;
        const int nquad = NB * plane / 4;
        pw_kernel<20><<<dim3((nquad + 255) / 256, 4), 256>>>(bufB, pw2_w, pw2_b, bufA,
                                                             40, plane, nquad);
    }

    // ---- block 3 (stride 1): dw 40ch on (10,32,96), pw 40->40 ----
    dw_s1_kernel<40, 10, 32, 96, 2><<<NB * 40 * 10 * 2, 256>>>(bufA, dw3_w, dw3_b, bufB);
    {
        const int plane = 10 * 32 * 96;
        const int nquad = NB * plane / 4;
        pw_kernel<40><<<dim3((nquad + 255) / 256, 4), 256>>>(bufB, pw3_w, pw3_b, bufA,
                                                             40, plane, nquad);
    }

    // ---- block 4 (stride 2): dw -> (40,5,16,48), pw 40->80 -> d_out ----
    {
        const int total = NB * 40 * 5 * 16 * 48;
        dw_s2_kernel<40, 10, 32, 96, 5, 16, 48>
            <<<(total + 255) / 256, 256>>>(bufA, dw4_w, dw4_b, bufB);
        const int plane = 5 * 16 * 48;
        const int nquad = NB * plane / 4;
        pw_kernel<40><<<dim3((nquad + 255) / 256, 8), 256>>>(bufB, pw4_w, pw4_b, out,
                                                             80, plane, nquad);
    }
}

// round 3
// speedup vs baseline: 1.6705x; 1.1838x over previous
#include <cuda_runtime.h>
#include <cstdint>

#define NB   8
#define NC   64
#define NH   64
#define NW   192
#define NP   20

// ping-pong scratch (157 MB each, .bss — allowed)
__device__ float g_bufA[NB * NP * NP * NH * NW];
__device__ float g_bufB[NB * NP * NP * NH * NW];

__device__ __forceinline__ float leaky(float x) {
    return x > 0.0f ? x : 0.1f * x;
}

// ---------------------------------------------------------------------------
// Correlation: block = (h, di, b). Channels processed in 2 chunks of 32 so
// smem = 32*(192+212)*4 = 51,712 B -> 4 blocks/SM = 16 warps/SM.
// 128 threads, thread tile 8w x 4dj (120 active).
// ---------------------------------------------------------------------------
__global__ void __launch_bounds__(128, 4)
corr_kernel(const float* __restrict__ rgb,
            const float* __restrict__ dep,
            float* __restrict__ out)
{
    const int h  = blockIdx.x;
    const int di = blockIdx.y;
    const int b  = blockIdx.z;
    const int tid = threadIdx.x;

    extern __shared__ float sm[];
    float* sm_rgb = sm;               // 32*192
    float* sm_dep = sm + 32 * 192;    // 32*212  (x = w + dj)

    const int wg  = tid % 24;
    const int djg = tid / 24;
    const int w0  = wg * 8;
    const int dj0 = djg * 4;
    const int x0  = w0 + dj0;          // 4-aligned
    const bool active = (tid < 120);

    const int hr = h + di - 10;
    if (hr < 0 || hr >= NH) {
        // entire output row is zero
        if (active) {
            float4 z = {0.f, 0.f, 0.f, 0.f};
            #pragma unroll
            for (int j = 0; j < 4; j++) {
                size_t base = ((((size_t)b * NP + di) * NP + (dj0 + j)) * NH + h) * NW + w0;
                *(float4*)&out[base]     = z;
                *(float4*)&out[base + 4] = z;
            }
        }
        return;
    }

    float acc[4][8];
    #pragma unroll
    for (int j = 0; j < 4; j++)
        #pragma unroll
        for (int i = 0; i < 8; i++) acc[j][i] = 0.0f;

    #pragma unroll
    for (int ch = 0; ch < 2; ch++) {
        const float* rgbb = rgb + ((size_t)b * NC + ch * 32) * (NH * NW);
        const float* depb = dep + ((size_t)b * NC + ch * 32) * (NH * NW);

        __syncthreads();   // previous chunk's compute done before overwrite

        // rgb chunk: 32 ch x 192 w (float4)
        for (int i = tid; i < 32 * 48; i += 128) {
            int c = i / 48;
            int w4 = (i - c * 48) * 4;
            *(float4*)&sm_rgb[c * 192 + w4] =
                *(const float4*)&rgbb[(size_t)c * (NH * NW) + h * NW + w4];
        }
        // depth chunk, padded to x in [0,212)
        for (int i = tid; i < 32 * 212; i += 128) {
            int c = i / 212;
            int x = i - c * 212;
            int xr = x - 10;
            float v = 0.0f;
            if (xr >= 0 && xr < NW)
                v = depb[(size_t)c * (NH * NW) + hr * NW + xr];
            sm_dep[i] = v;
        }
        __syncthreads();

        if (!active) continue;

        #pragma unroll 4
        for (int c = 0; c < 32; c++) {
            float4 r0 = *(const float4*)&sm_rgb[c * 192 + w0];
            float4 r1 = *(const float4*)&sm_rgb[c * 192 + w0 + 4];
            float4 d0 = *(const float4*)&sm_dep[c * 212 + x0];
            float4 d1 = *(const float4*)&sm_dep[c * 212 + x0 + 4];
            float4 d2 = *(const float4*)&sm_dep[c * 212 + x0 + 8];
            float r[8]   = {r0.x, r0.y, r0.z, r0.w, r1.x, r1.y, r1.z, r1.w};
            float dv[12] = {d0.x, d0.y, d0.z, d0.w,
                            d1.x, d1.y, d1.z, d1.w,
                            d2.x, d2.y, d2.z, d2.w};
            #pragma unroll
            for (int j = 0; j < 4; j++)
                #pragma unroll
                for (int i = 0; i < 8; i++)
                    acc[j][i] += r[i] * dv[i + j];
        }
    }

    if (!active) return;
    #pragma unroll
    for (int j = 0; j < 4; j++) {
        size_t base = ((((size_t)b * NP + di) * NP + (dj0 + j)) * NH + h) * NW + w0;
        float4 o0 = {acc[j][0], acc[j][1], acc[j][2], acc[j][3]};
        float4 o1 = {acc[j][4], acc[j][5], acc[j][6], acc[j][7]};
        *(float4*)&out[base]     = o0;
        *(float4*)&out[base + 4] = o1;
    }
}

// ---------------------------------------------------------------------------
// Depthwise 3x3x3, stride 1, pad 1, + leaky. All dims constexpr.
// block = (n, c, d, h-tile of 16). smem: 3 z-planes x 18 rows x (W+4)
// ---------------------------------------------------------------------------
template<int C, int D, int H, int W, int HT>
__global__ void dw_s1_kernel(const float* __restrict__ in,
                             const float* __restrict__ wgt,
                             const float* __restrict__ bias,
                             float* __restrict__ out)
{
    constexpr int SW = W + 4;
    __shared__ float smp[3 * 18 * SW];

    int bx = blockIdx.x;
    const int ht = bx % HT;  bx /= HT;
    const int d  = bx % D;   bx /= D;
    const int c  = bx % C;
    const int n  = bx / C;
    const int h0 = ht * 16;
    const int tid = threadIdx.x;

    const float* inb = in + (size_t)(n * C + c) * D * H * W;

    constexpr int total = 3 * 18 * SW;
    for (int i = tid; i < total; i += blockDim.x) {
        int z = i / (18 * SW);
        int r = i - z * 18 * SW;
        int y = r / SW;
        int x = r - y * SW;
        int zi = d - 1 + z, yi = h0 - 1 + y, xi = x - 1;
        float v = 0.0f;
        if (zi >= 0 && zi < D && yi >= 0 && yi < H && xi >= 0 && xi < W)
            v = inb[(size_t)zi * H * W + yi * W + xi];
        smp[i] = v;
    }

    float wt[27];
    #pragma unroll
    for (int k = 0; k < 27; k++) wt[k] = __ldg(&wgt[c * 27 + k]);
    const float bb = __ldg(&bias[c]);
    __syncthreads();

    constexpr int wq = W / 4;
    constexpr int items = 16 * wq;
    for (int it = tid; it < items; it += blockDim.x) {
        int hl  = it / wq;
        int wg4 = (it - hl * wq) * 4;
        float a0 = bb, a1 = bb, a2 = bb, a3 = bb;
        #pragma unroll
        for (int z = 0; z < 3; z++)
            #pragma unroll
            for (int y = 0; y < 3; y++) {
                const float* row = &smp[(z * 18 + hl + y) * SW + wg4];
                float4 v4 = *(const float4*)row;
                float v4a = row[4];
                float v5  = row[5];
                float w0 = wt[(z * 3 + y) * 3 + 0];
                float w1 = wt[(z * 3 + y) * 3 + 1];
                float w2 = wt[(z * 3 + y) * 3 + 2];
                a0 += w0 * v4.x + w1 * v4.y + w2 * v4.z;
                a1 += w0 * v4.y + w1 * v4.z + w2 * v4.w;
                a2 += w0 * v4.z + w1 * v4.w + w2 * v4a;
                a3 += w0 * v4.w + w1 * v4a  + w2 * v5;
            }
        float4 o = {leaky(a0), leaky(a1), leaky(a2), leaky(a3)};
        *(float4*)&out[((size_t)(n * C + c) * D + d) * H * W + (h0 + hl) * W + wg4] = o;
    }
}

// ---------------------------------------------------------------------------
// Depthwise 3x3x3, stride 2, pad 1, + leaky. Dims constexpr, 1 thread/output.
// ---------------------------------------------------------------------------
template<int C, int D, int H, int W, int Do, int Ho, int Wo>
__global__ void dw_s2_kernel(const float* __restrict__ in,
                             const float* __restrict__ wgt,
                             const float* __restrict__ bias,
                             float* __restrict__ out)
{
    constexpr int total = NB * C * Do * Ho * Wo;
    int idx = blockIdx.x * blockDim.x + threadIdx.x;
    if (idx >= total) return;
    int t = idx;
    const int wo = t % Wo; t /= Wo;
    const int ho = t % Ho; t /= Ho;
    const int dd = t % Do; t /= Do;
    const int c  = t % C;
    const int n  = t / C;

    const float* inb = in + (size_t)(n * C + c) * D * H * W;
    const float* wp  = &wgt[c * 27];
    float acc = __ldg(&bias[c]);
    #pragma unroll
    for (int kz = 0; kz < 3; kz++) {
        int zi = 2 * dd - 1 + kz;
        if (zi < 0 || zi >= D) continue;
        #pragma unroll
        for (int ky = 0; ky < 3; ky++) {
            int yi = 2 * ho - 1 + ky;
            if (yi < 0 || yi >= H) continue;
            #pragma unroll
            for (int kx = 0; kx < 3; kx++) {
                int xi = 2 * wo - 1 + kx;
                if (xi < 0 || xi >= W) continue;
                acc += __ldg(&wp[(kz * 3 + ky) * 3 + kx]) *
                       __ldg(&inb[(size_t)zi * H * W + yi * W + xi]);
            }
        }
    }
    out[idx] = leaky(acc);
}

// ---------------------------------------------------------------------------
// Pointwise Cin->Cout + leaky. Thread = 4 contiguous positions x COT-co tile.
// ---------------------------------------------------------------------------
template<int Cin, int COT>
__global__ void pw_kernel(const float* __restrict__ in,
                          const float* __restrict__ wgt,
                          const float* __restrict__ bias,
                          float* __restrict__ out,
                          int Cout, int plane, int nquad)
{
    __shared__ float sw[COT * Cin];
    __shared__ float sb[COT];

    const int co0 = blockIdx.y * COT;
    const int tid = threadIdx.x;

    for (int i = tid; i < COT * Cin; i += blockDim.x) {
        int j  = i / Cin;
        int ci = i - j * Cin;
        sw[i] = wgt[(co0 + j) * Cin + ci];
    }
    if (tid < COT) sb[tid] = bias[co0 + tid];
    __syncthreads();

    const int t = blockIdx.x * blockDim.x + tid;
    if (t >= nquad) return;
    const int s0 = t * 4;
    const int n  = s0 / plane;
    const int p  = s0 - n * plane;

    const float* inb = in + (size_t)n * Cin * plane + p;

    float acc[COT][4];
    #pragma unroll
    for (int j = 0; j < COT; j++) {
        float bv = sb[j];
        acc[j][0] = bv; acc[j][1] = bv; acc[j][2] = bv; acc[j][3] = bv;
    }

    #pragma unroll
    for (int ci = 0; ci < Cin; ci++) {
        float4 x4 = *(const float4*)&inb[(size_t)ci * plane];
        #pragma unroll
        for (int j = 0; j < COT; j++) {
            float wv = sw[j * Cin + ci];
            acc[j][0] += wv * x4.x;
            acc[j][1] += wv * x4.y;
            acc[j][2] += wv * x4.z;
            acc[j][3] += wv * x4.w;
        }
    }

    float* ob = out + (size_t)n * Cout * plane + p;
    #pragma unroll
    for (int j = 0; j < COT; j++) {
        float4 o = {leaky(acc[j][0]), leaky(acc[j][1]),
                    leaky(acc[j][2]), leaky(acc[j][3])};
        *(float4*)&ob[(size_t)(co0 + j) * plane] = o;
    }
}

// ---------------------------------------------------------------------------
extern "C" void kernel_launch(void* const* d_in, const int* in_sizes, int n_in,
                              void* d_out, int out_size)
{
    const float* rgb   = (const float*)d_in[0];
    const float* dep   = (const float*)d_in[1];
    const float* dw1_w = (const float*)d_in[2];
    const float* dw1_b = (const float*)d_in[3];
    const float* pw1_w = (const float*)d_in[4];
    const float* pw1_b = (const float*)d_in[5];
    const float* dw2_w = (const float*)d_in[6];
    const float* dw2_b = (const float*)d_in[7];
    const float* pw2_w = (const float*)d_in[8];
    const float* pw2_b = (const float*)d_in[9];
    const float* dw3_w = (const float*)d_in[10];
    const float* dw3_b = (const float*)d_in[11];
    const float* pw3_w = (const float*)d_in[12];
    const float* pw3_b = (const float*)d_in[13];
    const float* dw4_w = (const float*)d_in[14];
    const float* dw4_b = (const float*)d_in[15];
    const float* pw4_w = (const float*)d_in[16];
    const float* pw4_b = (const float*)d_in[17];
    float* out = (float*)d_out;

    float *bufA = nullptr, *bufB = nullptr;
    cudaGetSymbolAddress((void**)&bufA, g_bufA);
    cudaGetSymbolAddress((void**)&bufB, g_bufB);

    // ---- correlation -> bufA ----
    const int smem_corr = (32 * 192 + 32 * 212) * 4;   // 51,712 B
    cudaFuncSetAttribute(corr_kernel,
                         cudaFuncAttributeMaxDynamicSharedMemorySize, smem_corr);
    corr_kernel<<<dim3(NH, NP, NB), 128, smem_corr>>>(rgb, dep, bufA);

    // ---- block 1 (stride 1): dw 20ch on (20,64,192), pw 20->20 ----
    dw_s1_kernel<20, 20, 64, 192, 4><<<NB * 20 * 20 * 4, 256>>>(bufA, dw1_w, dw1_b, bufB);
    {
        const int plane = 20 * 64 * 192;
        const int nquad = NB * plane / 4;
        pw_kernel<20, 20><<<dim3((nquad + 255) / 256, 1), 256>>>(bufB, pw1_w, pw1_b, bufA,
                                                                 20, plane, nquad);
    }

    // ---- block 2 (stride 2): dw -> (20,10,32,96), pw 20->40 ----
    {
        const int total = NB * 20 * 10 * 32 * 96;
        dw_s2_kernel<20, 20, 64, 192, 10, 32, 96>
            <<<(total + 255) / 256, 256>>>(bufA, dw2_w, dw2_b, bufB);
        const int plane = 10 * 32 * 96;
        const int nquad = NB * plane / 4;
        pw_kernel<20, 20><<<dim3((nquad + 255) / 256, 2), 256>>>(bufB, pw2_w, pw2_b, bufA,
                                                                 40, plane, nquad);
    }

    // ---- block 3 (stride 1): dw 40ch on (10,32,96), pw 40->40 ----
    dw_s1_kernel<40, 10, 32, 96, 2><<<NB * 40 * 10 * 2, 256>>>(bufA, dw3_w, dw3_b, bufB);
    {
        const int plane = 10 * 32 * 96;
        const int nquad = NB * plane / 4;
        pw_kernel<40, 20><<<dim3((nquad + 255) / 256, 2), 256>>>(bufB, pw3_w, pw3_b, bufA,
                                                                 40, plane, nquad);
    }

    // ---- block 4 (stride 2): dw -> (40,5,16,48), pw 40->80 -> d_out ----
    {
        const int total = NB * 40 * 5 * 16 * 48;
        dw_s2_kernel<40, 10, 32, 96, 5, 16, 48>
            <<<(total + 255) / 256, 256>>>(bufA, dw4_w, dw4_b, bufB);
        const int plane = 5 * 16 * 48;
        const int nquad = NB * plane / 4;
        pw_kernel<40, 20><<<dim3((nquad + 255) / 256, 4), 256>>>(bufB, pw4_w, pw4_b, out,
                                                                 80, plane, nquad);
    }
}

// round 4
// speedup vs baseline: 2.2065x; 1.3208x over previous
#include <cuda_runtime.h>
#include <cstdint>

#define NB   8
#define NC   64
#define NH   64
#define NW   192
#define NP   20

// ping-pong scratch (157 MB each, .bss — allowed)
__device__ float g_bufA[NB * NP * NP * NH * NW];
__device__ float g_bufB[NB * NP * NP * NH * NW];

__device__ __forceinline__ float leaky(float x) {
    return x > 0.0f ? x : 0.1f * x;
}

// ---------------------------------------------------------------------------
// Correlation: block = (h, di-pair, b). 16-channel chunks, 2 depth rows.
// smem: rgb[16][192] + dep[2][16][212] = 39,424 B -> 4 blocks/SM.
// 128 threads; thread tile 8w x 4dj x 2di (120 active).
// ---------------------------------------------------------------------------
__global__ void __launch_bounds__(128, 4)
corr_kernel(const float* __restrict__ rgb,
            const float* __restrict__ dep,
            float* __restrict__ out)
{
    const int h  = blockIdx.x;
    const int dp = blockIdx.y;          // di = 2*dp, 2*dp+1
    const int b  = blockIdx.z;
    const int tid = threadIdx.x;

    extern __shared__ float sm[];
    float* sm_rgb = sm;                  // 16*192
    float* sm_dep = sm + 16 * 192;       // 2 * 16 * 212   sm_dep[x] = dep[x-10]

    const int wg  = tid % 24;
    const int djg = tid / 24;
    const int w0  = wg * 8;
    const int dj0 = djg * 4;
    const int x0  = w0 + dj0;            // 4-aligned
    const bool active = (tid < 120);

    const int hr0 = h + 2 * dp - 10;
    const int hr1 = hr0 + 1;
    const bool v0r = (hr0 >= 0 && hr0 < NH);
    const bool v1r = (hr1 >= 0 && hr1 < NH);

    if (!v0r && !v1r) {
        if (active) {
            float4 z = {0.f, 0.f, 0.f, 0.f};
            #pragma unroll
            for (int r = 0; r < 2; r++)
                #pragma unroll
                for (int j = 0; j < 4; j++) {
                    size_t base = ((((size_t)b * NP + 2 * dp + r) * NP + (dj0 + j)) * NH + h) * NW + w0;
                    *(float4*)&out[base]     = z;
                    *(float4*)&out[base + 4] = z;
                }
        }
        return;
    }

    float acc[2][4][8];
    #pragma unroll
    for (int r = 0; r < 2; r++)
        #pragma unroll
        for (int j = 0; j < 4; j++)
            #pragma unroll
            for (int i = 0; i < 8; i++) acc[r][j][i] = 0.0f;

    const size_t bbase = (size_t)b * NC * NH * NW;

    #pragma unroll 1
    for (int cc = 0; cc < 4; cc++) {
        const int c0 = cc * 16;
        if (cc) __syncthreads();     // previous chunk compute done

        // rgb chunk: 16 ch x 192 w  = 768 float4, 6 per thread
        #pragma unroll
        for (int u = 0; u < 6; u++) {
            int i = tid + u * 128;               // < 768
            int c = i / 48;
            int k4 = (i - c * 48) * 4;
            *(float4*)&sm_rgb[c * 192 + k4] =
                *(const float4*)&rgb[bbase + (size_t)(c0 + c) * (NH * NW) + h * NW + k4];
        }

        // depth rows (interior): 2 rows x 16 ch x 48 float4 = 1536, 12/thread
        #pragma unroll
        for (int u = 0; u < 12; u++) {
            int i = tid + u * 128;               // < 1536
            int rc = i / 48;
            int k4 = (i - rc * 48) * 4;
            int r  = rc >> 4;
            int c  = rc & 15;
            int hr = r ? hr1 : hr0;
            bool vr = r ? v1r : v0r;
            float4 v = {0.f, 0.f, 0.f, 0.f};
            if (vr)
                v = *(const float4*)&dep[bbase + (size_t)(c0 + c) * (NH * NW) + hr * NW + k4];
            float* dst = &sm_dep[(r * 16 + c) * 212 + 10 + k4];
            *(float2*)(dst)     = make_float2(v.x, v.y);
            *(float2*)(dst + 2) = make_float2(v.z, v.w);
        }

        // depth edges: x in [0,10) u [202,212): 2*16*20 = 640, 5/thread
        #pragma unroll
        for (int u = 0; u < 5; u++) {
            int i = tid + u * 128;               // < 640
            int rc = i / 20;
            int p  = i - rc * 20;
            int x  = (p < 10) ? p : 192 + p;     // 0..9 or 202..211
            sm_dep[rc * 212 + x] = 0.0f;
        }
        __syncthreads();

        if (!active) continue;

        #pragma unroll 2
        for (int c = 0; c < 16; c++) {
            float4 r0 = *(const float4*)&sm_rgb[c * 192 + w0];
            float4 r1 = *(const float4*)&sm_rgb[c * 192 + w0 + 4];
            float rr[8] = {r0.x, r0.y, r0.z, r0.w, r1.x, r1.y, r1.z, r1.w};
            #pragma unroll
            for (int r = 0; r < 2; r++) {
                const float* dr = &sm_dep[(r * 16 + c) * 212 + x0];
                float4 d0 = *(const float4*)(dr);
                float4 d1 = *(const float4*)(dr + 4);
                float4 d2 = *(const float4*)(dr + 8);
                float dv[12] = {d0.x, d0.y, d0.z, d0.w,
                                d1.x, d1.y, d1.z, d1.w,
                                d2.x, d2.y, d2.z, d2.w};
                #pragma unroll
                for (int j = 0; j < 4; j++)
                    #pragma unroll
                    for (int i = 0; i < 8; i++)
                        acc[r][j][i] += rr[i] * dv[i + j];
            }
        }
    }

    if (!active) return;
    #pragma unroll
    for (int r = 0; r < 2; r++)
        #pragma unroll
        for (int j = 0; j < 4; j++) {
            size_t base = ((((size_t)b * NP + 2 * dp + r) * NP + (dj0 + j)) * NH + h) * NW + w0;
            float4 o0 = {acc[r][j][0], acc[r][j][1], acc[r][j][2], acc[r][j][3]};
            float4 o1 = {acc[r][j][4], acc[r][j][5], acc[r][j][6], acc[r][j][7]};
            *(float4*)&out[base]     = o0;
            *(float4*)&out[base + 4] = o1;
        }
}

// ---------------------------------------------------------------------------
// Depthwise 3x3x3, stride 1, pad 1, + leaky. Vectorized smem fill.
// block = (n, c, d, h-tile of 16). smem: 3 z-planes x 18 rows x 200
// layout: smp[row][x], x = xi + 4  (left pad 4 keeps fill+read aligned)
// ---------------------------------------------------------------------------
template<int C, int D, int H, int W, int HT>
__global__ void dw_s1_kernel(const float* __restrict__ in,
                             const float* __restrict__ wgt,
                             const float* __restrict__ bias,
                             float* __restrict__ out)
{
    constexpr int SW = W + 8;            // W=192 -> 200; W=96 -> 104
    __shared__ float smp[3 * 18 * SW];

    int bx = blockIdx.x;
    const int ht = bx % HT;  bx /= HT;
    const int d  = bx % D;   bx /= D;
    const int c  = bx % C;
    const int n  = bx / C;
    const int h0 = ht * 16;
    const int tid = threadIdx.x;

    const float* inb = in + (size_t)(n * C + c) * D * H * W;

    // interior fill: 54 rows x (W/4) float4
    constexpr int WQ = W / 4;
    constexpr int nf4 = 54 * WQ;
    for (int i = tid; i < nf4; i += blockDim.x) {
        int row = i / WQ;
        int k4  = (i - row * WQ) * 4;
        int z = row / 18;
        int y = row - z * 18;
        int zi = d - 1 + z, yi = h0 - 1 + y;
        float4 v = {0.f, 0.f, 0.f, 0.f};
        if (zi >= 0 && zi < D && yi >= 0 && yi < H)
            v = *(const float4*)&inb[(size_t)zi * H * W + yi * W + k4];
        *(float4*)&smp[row * SW + 4 + k4] = v;
    }
    // edge zeros: x in {0..3, W+4..W+7} per row
    for (int i = tid; i < 54 * 8; i += blockDim.x) {
        int row = i / 8;
        int p   = i - row * 8;
        int x   = (p < 4) ? p : W + p;
        smp[row * SW + x] = 0.0f;
    }

    float wt[27];
    #pragma unroll
    for (int k = 0; k < 27; k++) wt[k] = __ldg(&wgt[c * 27 + k]);
    const float bb = __ldg(&bias[c]);
    __syncthreads();

    constexpr int items = 16 * WQ;
    for (int it = tid; it < items; it += blockDim.x) {
        int hl  = it / WQ;
        int wg4 = (it - hl * WQ) * 4;
        float a0 = bb, a1 = bb, a2 = bb, a3 = bb;
        #pragma unroll
        for (int z = 0; z < 3; z++)
            #pragma unroll
            for (int y = 0; y < 3; y++) {
                const float* row = &smp[(z * 18 + hl + y) * SW];
                float m1  = row[wg4 + 3];
                float4 v4 = *(const float4*)&row[wg4 + 4];
                float p   = row[wg4 + 8];
                float w0 = wt[(z * 3 + y) * 3 + 0];
                float w1 = wt[(z * 3 + y) * 3 + 1];
                float w2 = wt[(z * 3 + y) * 3 + 2];
                a0 += w0 * m1   + w1 * v4.x + w2 * v4.y;
                a1 += w0 * v4.x + w1 * v4.y + w2 * v4.z;
                a2 += w0 * v4.y + w1 * v4.z + w2 * v4.w;
                a3 += w0 * v4.z + w1 * v4.w + w2 * p;
            }
        float4 o = {leaky(a0), leaky(a1), leaky(a2), leaky(a3)};
        *(float4*)&out[((size_t)(n * C + c) * D + d) * H * W + (h0 + hl) * W + wg4] = o;
    }
}

// ---------------------------------------------------------------------------
// Depthwise 3x3x3, stride 2, pad 1, + leaky. Thread = 4 consecutive wo.
// Per (kz,ky) row: 2x LDG.128 + 1 scalar covers all 9 needed inputs.
// ---------------------------------------------------------------------------
template<int C, int D, int H, int W, int Do, int Ho, int Wo>
__global__ void dw_s2_kernel(const float* __restrict__ in,
                             const float* __restrict__ wgt,
                             const float* __restrict__ bias,
                             float* __restrict__ out)
{
    constexpr int WQ = Wo / 4;
    constexpr int total = NB * C * Do * Ho * WQ;
    int idx = blockIdx.x * blockDim.x + threadIdx.x;
    if (idx >= total) return;
    int t = idx;
    const int q  = t % WQ; t /= WQ;
    const int ho = t % Ho; t /= Ho;
    const int dd = t % Do; t /= Do;
    const int c  = t % C;
    const int n  = t / C;
    const int g  = q * 8;                // 2*wo0, wo0 = 4q

    const float* inb = in + (size_t)(n * C + c) * D * H * W;
    const float* wp  = &wgt[c * 27];
    const float bb = __ldg(&bias[c]);
    float a0 = bb, a1 = bb, a2 = bb, a3 = bb;

    #pragma unroll
    for (int kz = 0; kz < 3; kz++) {
        int zi = 2 * dd - 1 + kz;
        if (zi < 0 || zi >= D) continue;
        #pragma unroll
        for (int ky = 0; ky < 3; ky++) {
            int yi = 2 * ho - 1 + ky;
            if (yi < 0 || yi >= H) continue;
            const float* base = &inb[(size_t)zi * H * W + yi * W];
            float  m1 = (g > 0) ? __ldg(&base[g - 1]) : 0.0f;
            float4 v0 = *(const float4*)&base[g];
            float4 v1 = *(const float4*)&base[g + 4];
            float xv[9] = {m1, v0.x, v0.y, v0.z, v0.w, v1.x, v1.y, v1.z, v1.w};
            float w0 = __ldg(&wp[(kz * 3 + ky) * 3 + 0]);
            float w1 = __ldg(&wp[(kz * 3 + ky) * 3 + 1]);
            float w2 = __ldg(&wp[(kz * 3 + ky) * 3 + 2]);
            a0 += w0 * xv[0] + w1 * xv[1] + w2 * xv[2];
            a1 += w0 * xv[2] + w1 * xv[3] + w2 * xv[4];
            a2 += w0 * xv[4] + w1 * xv[5] + w2 * xv[6];
            a3 += w0 * xv[6] + w1 * xv[7] + w2 * xv[8];
        }
    }
    float4 o = {leaky(a0), leaky(a1), leaky(a2), leaky(a3)};
    size_t obase = ((((size_t)n * C + c) * Do + dd) * Ho + ho) * Wo + q * 4;
    *(float4*)&out[obase] = o;
}

// ---------------------------------------------------------------------------
// Pointwise Cin->Cout + leaky. Thread = 4 contiguous positions x COT-co tile.
// ---------------------------------------------------------------------------
template<int Cin, int COT>
__global__ void pw_kernel(const float* __restrict__ in,
                          const float* __restrict__ wgt,
                          const float* __restrict__ bias,
                          float* __restrict__ out,
                          int Cout, int plane, int nquad)
{
    __shared__ float sw[COT * Cin];
    __shared__ float sb[COT];

    const int co0 = blockIdx.y * COT;
    const int tid = threadIdx.x;

    for (int i = tid; i < COT * Cin; i += blockDim.x) {
        int j  = i / Cin;
        int ci = i - j * Cin;
        sw[i] = wgt[(co0 + j) * Cin + ci];
    }
    if (tid < COT) sb[tid] = bias[co0 + tid];
    __syncthreads();

    const int t = blockIdx.x * blockDim.x + tid;
    if (t >= nquad) return;
    const int s0 = t * 4;
    const int n  = s0 / plane;
    const int p  = s0 - n * plane;

    const float* inb = in + (size_t)n * Cin * plane + p;

    float acc[COT][4];
    #pragma unroll
    for (int j = 0; j < COT; j++) {
        float bv = sb[j];
        acc[j][0] = bv; acc[j][1] = bv; acc[j][2] = bv; acc[j][3] = bv;
    }

    #pragma unroll
    for (int ci = 0; ci < Cin; ci++) {
        float4 x4 = *(const float4*)&inb[(size_t)ci * plane];
        #pragma unroll
        for (int j = 0; j < COT; j++) {
            float wv = sw[j * Cin + ci];
            acc[j][0] += wv * x4.x;
            acc[j][1] += wv * x4.y;
            acc[j][2] += wv * x4.z;
            acc[j][3] += wv * x4.w;
        }
    }

    float* ob = out + (size_t)n * Cout * plane + p;
    #pragma unroll
    for (int j = 0; j < COT; j++) {
        float4 o = {leaky(acc[j][0]), leaky(acc[j][1]),
                    leaky(acc[j][2]), leaky(acc[j][3])};
        *(float4*)&ob[(size_t)(co0 + j) * plane] = o;
    }
}

// ---------------------------------------------------------------------------
extern "C" void kernel_launch(void* const* d_in, const int* in_sizes, int n_in,
                              void* d_out, int out_size)
{
    const float* rgb   = (const float*)d_in[0];
    const float* dep   = (const float*)d_in[1];
    const float* dw1_w = (const float*)d_in[2];
    const float* dw1_b = (const float*)d_in[3];
    const float* pw1_w = (const float*)d_in[4];
    const float* pw1_b = (const float*)d_in[5];
    const float* dw2_w = (const float*)d_in[6];
    const float* dw2_b = (const float*)d_in[7];
    const float* pw2_w = (const float*)d_in[8];
    const float* pw2_b = (const float*)d_in[9];
    const float* dw3_w = (const float*)d_in[10];
    const float* dw3_b = (const float*)d_in[11];
    const float* pw3_w = (const float*)d_in[12];
    const float* pw3_b = (const float*)d_in[13];
    const float* dw4_w = (const float*)d_in[14];
    const float* dw4_b = (const float*)d_in[15];
    const float* pw4_w = (const float*)d_in[16];
    const float* pw4_b = (const float*)d_in[17];
    float* out = (float*)d_out;

    float *bufA = nullptr, *bufB = nullptr;
    cudaGetSymbolAddress((void**)&bufA, g_bufA);
    cudaGetSymbolAddress((void**)&bufB, g_bufB);

    // ---- correlation -> bufA ----
    const int smem_corr = (16 * 192 + 2 * 16 * 212) * 4;   // 39,424 B
    cudaFuncSetAttribute(corr_kernel,
                         cudaFuncAttributeMaxDynamicSharedMemorySize, smem_corr);
    corr_kernel<<<dim3(NH, NP / 2, NB), 128, smem_corr>>>(rgb, dep, bufA);

    // ---- block 1 (stride 1): dw 20ch on (20,64,192), pw 20->20 ----
    dw_s1_kernel<20, 20, 64, 192, 4><<<NB * 20 * 20 * 4, 256>>>(bufA, dw1_w, dw1_b, bufB);
    {
        const int plane = 20 * 64 * 192;
        const int nquad = NB * plane / 4;
        pw_kernel<20, 20><<<dim3((nquad + 255) / 256, 1), 256>>>(bufB, pw1_w, pw1_b, bufA,
                                                                 20, plane, nquad);
    }

    // ---- block 2 (stride 2): dw -> (20,10,32,96), pw 20->40 ----
    {
        const int threads = NB * 20 * 10 * 32 * (96 / 4);
        dw_s2_kernel<20, 20, 64, 192, 10, 32, 96>
            <<<(threads + 255) / 256, 256>>>(bufA, dw2_w, dw2_b, bufB);
        const int plane = 10 * 32 * 96;
        const int nquad = NB * plane / 4;
        pw_kernel<20, 20><<<dim3((nquad + 255) / 256, 2), 256>>>(bufB, pw2_w, pw2_b, bufA,
                                                                 40, plane, nquad);
    }

    // ---- block 3 (stride 1): dw 40ch on (10,32,96), pw 40->40 ----
    dw_s1_kernel<40, 10, 32, 96, 2><<<NB * 40 * 10 * 2, 256>>>(bufA, dw3_w, dw3_b, bufB);
    {
        const int plane = 10 * 32 * 96;
        const int nquad = NB * plane / 4;
        pw_kernel<40, 20><<<dim3((nquad + 255) / 256, 2), 256>>>(bufB, pw3_w, pw3_b, bufA,
                                                                 40, plane, nquad);
    }

    // ---- block 4 (stride 2): dw -> (40,5,16,48), pw 40->80 -> d_out ----
    {
        const int threads = NB * 40 * 5 * 16 * (48 / 4);
        dw_s2_kernel<40, 10, 32, 96, 5, 16, 48>
            <<<(threads + 255) / 256, 256>>>(bufA, dw4_w, dw4_b, bufB);
        const int plane = 5 * 16 * 48;
        const int nquad = NB * plane / 4;
        pw_kernel<40, 20><<<dim3((nquad + 255) / 256, 4), 256>>>(bufB, pw4_w, pw4_b, out,
                                                                 80, plane, nquad);
    }
}

// round 5
// speedup vs baseline: 2.2086x; 1.0010x over previous
#include <cuda_runtime.h>
#include <cstdint>

#define NB   8
#define NC   64
#define NH   64
#define NW   192
#define NP   20

// ping-pong scratch (157 MB each, .bss — allowed)
__device__ float g_bufA[NB * NP * NP * NH * NW];
__device__ float g_bufB[NB * NP * NP * NH * NW];

__device__ __forceinline__ float leaky(float x) {
    return x > 0.0f ? x : 0.1f * x;
}

// ---------------------------------------------------------------------------
// Correlation: block = (h, di-pair, b). 16-channel chunks, 2 depth rows.
// smem: rgb[16][192] + dep[2][16][212] = 39,424 B -> 4 blocks/SM.
// 128 threads; thread tile 8w x 4dj x 2di (120 active).
// ---------------------------------------------------------------------------
__global__ void __launch_bounds__(128, 4)
corr_kernel(const float* __restrict__ rgb,
            const float* __restrict__ dep,
            float* __restrict__ out)
{
    const int h  = blockIdx.x;
    const int dp = blockIdx.y;          // di = 2*dp, 2*dp+1
    const int b  = blockIdx.z;
    const int tid = threadIdx.x;

    extern __shared__ float sm[];
    float* sm_rgb = sm;                  // 16*192
    float* sm_dep = sm + 16 * 192;       // 2 * 16 * 212   sm_dep[x] = dep[x-10]

    const int wg  = tid % 24;
    const int djg = tid / 24;
    const int w0  = wg * 8;
    const int dj0 = djg * 4;
    const int x0  = w0 + dj0;            // 4-aligned
    const bool active = (tid < 120);

    const int hr0 = h + 2 * dp - 10;
    const int hr1 = hr0 + 1;
    const bool v0r = (hr0 >= 0 && hr0 < NH);
    const bool v1r = (hr1 >= 0 && hr1 < NH);

    if (!v0r && !v1r) {
        if (active) {
            float4 z = {0.f, 0.f, 0.f, 0.f};
            #pragma unroll
            for (int r = 0; r < 2; r++)
                #pragma unroll
                for (int j = 0; j < 4; j++) {
                    size_t base = ((((size_t)b * NP + 2 * dp + r) * NP + (dj0 + j)) * NH + h) * NW + w0;
                    *(float4*)&out[base]     = z;
                    *(float4*)&out[base + 4] = z;
                }
        }
        return;
    }

    float acc[2][4][8];
    #pragma unroll
    for (int r = 0; r < 2; r++)
        #pragma unroll
        for (int j = 0; j < 4; j++)
            #pragma unroll
            for (int i = 0; i < 8; i++) acc[r][j][i] = 0.0f;

    const size_t bbase = (size_t)b * NC * NH * NW;

    #pragma unroll 1
    for (int cc = 0; cc < 4; cc++) {
        const int c0 = cc * 16;
        if (cc) __syncthreads();     // previous chunk compute done

        // rgb chunk: 16 ch x 192 w  = 768 float4, 6 per thread
        #pragma unroll
        for (int u = 0; u < 6; u++) {
            int i = tid + u * 128;               // < 768
            int c = i / 48;
            int k4 = (i - c * 48) * 4;
            *(float4*)&sm_rgb[c * 192 + k4] =
                *(const float4*)&rgb[bbase + (size_t)(c0 + c) * (NH * NW) + h * NW + k4];
        }

        // depth rows (interior): 2 rows x 16 ch x 48 float4 = 1536, 12/thread
        #pragma unroll
        for (int u = 0; u < 12; u++) {
            int i = tid + u * 128;               // < 1536
            int rc = i / 48;
            int k4 = (i - rc * 48) * 4;
            int r  = rc >> 4;
            int c  = rc & 15;
            int hr = r ? hr1 : hr0;
            bool vr = r ? v1r : v0r;
            float4 v = {0.f, 0.f, 0.f, 0.f};
            if (vr)
                v = *(const float4*)&dep[bbase + (size_t)(c0 + c) * (NH * NW) + hr * NW + k4];
            float* dst = &sm_dep[(r * 16 + c) * 212 + 10 + k4];
            *(float2*)(dst)     = make_float2(v.x, v.y);
            *(float2*)(dst + 2) = make_float2(v.z, v.w);
        }

        // depth edges: x in [0,10) u [202,212): 2*16*20 = 640, 5/thread
        #pragma unroll
        for (int u = 0; u < 5; u++) {
            int i = tid + u * 128;               // < 640
            int rc = i / 20;
            int p  = i - rc * 20;
            int x  = (p < 10) ? p : 192 + p;     // 0..9 or 202..211
            sm_dep[rc * 212 + x] = 0.0f;
        }
        __syncthreads();

        if (!active) continue;

        #pragma unroll 2
        for (int c = 0; c < 16; c++) {
            float4 r0 = *(const float4*)&sm_rgb[c * 192 + w0];
            float4 r1 = *(const float4*)&sm_rgb[c * 192 + w0 + 4];
            float rr[8] = {r0.x, r0.y, r0.z, r0.w, r1.x, r1.y, r1.z, r1.w};
            #pragma unroll
            for (int r = 0; r < 2; r++) {
                const float* dr = &sm_dep[(r * 16 + c) * 212 + x0];
                float4 d0 = *(const float4*)(dr);
                float4 d1 = *(const float4*)(dr + 4);
                float4 d2 = *(const float4*)(dr + 8);
                float dv[12] = {d0.x, d0.y, d0.z, d0.w,
                                d1.x, d1.y, d1.z, d1.w,
                                d2.x, d2.y, d2.z, d2.w};
                #pragma unroll
                for (int j = 0; j < 4; j++)
                    #pragma unroll
                    for (int i = 0; i < 8; i++)
                        acc[r][j][i] += rr[i] * dv[i + j];
            }
        }
    }

    if (!active) return;
    #pragma unroll
    for (int r = 0; r < 2; r++)
        #pragma unroll
        for (int j = 0; j < 4; j++) {
            size_t base = ((((size_t)b * NP + 2 * dp + r) * NP + (dj0 + j)) * NH + h) * NW + w0;
            float4 o0 = {acc[r][j][0], acc[r][j][1], acc[r][j][2], acc[r][j][3]};
            float4 o1 = {acc[r][j][4], acc[r][j][5], acc[r][j][6], acc[r][j][7]};
            *(float4*)&out[base]     = o0;
            *(float4*)&out[base + 4] = o1;
        }
}

// ---------------------------------------------------------------------------
// Depthwise 3x3x3, stride 1, pad 1, + leaky. Vectorized smem fill.
// block = (n, c, d, h-tile of 16). smem: 3 z-planes x 18 rows x 200
// layout: smp[row][x], x = xi + 4  (left pad 4 keeps fill+read aligned)
// ---------------------------------------------------------------------------
template<int C, int D, int H, int W, int HT>
__global__ void dw_s1_kernel(const float* __restrict__ in,
                             const float* __restrict__ wgt,
                             const float* __restrict__ bias,
                             float* __restrict__ out)
{
    constexpr int SW = W + 8;            // W=192 -> 200; W=96 -> 104
    __shared__ float smp[3 * 18 * SW];

    int bx = blockIdx.x;
    const int ht = bx % HT;  bx /= HT;
    const int d  = bx % D;   bx /= D;
    const int c  = bx % C;
    const int n  = bx / C;
    const int h0 = ht * 16;
    const int tid = threadIdx.x;

    const float* inb = in + (size_t)(n * C + c) * D * H * W;

    // interior fill: 54 rows x (W/4) float4
    constexpr int WQ = W / 4;
    constexpr int nf4 = 54 * WQ;
    for (int i = tid; i < nf4; i += blockDim.x) {
        int row = i / WQ;
        int k4  = (i - row * WQ) * 4;
        int z = row / 18;
        int y = row - z * 18;
        int zi = d - 1 + z, yi = h0 - 1 + y;
        float4 v = {0.f, 0.f, 0.f, 0.f};
        if (zi >= 0 && zi < D && yi >= 0 && yi < H)
            v = *(const float4*)&inb[(size_t)zi * H * W + yi * W + k4];
        *(float4*)&smp[row * SW + 4 + k4] = v;
    }
    // edge zeros: x in {0..3, W+4..W+7} per row
    for (int i = tid; i < 54 * 8; i += blockDim.x) {
        int row = i / 8;
        int p   = i - row * 8;
        int x   = (p < 4) ? p : W + p;
        smp[row * SW + x] = 0.0f;
    }

    float wt[27];
    #pragma unroll
    for (int k = 0; k < 27; k++) wt[k] = __ldg(&wgt[c * 27 + k]);
    const float bb = __ldg(&bias[c]);
    __syncthreads();

    constexpr int items = 16 * WQ;
    for (int it = tid; it < items; it += blockDim.x) {
        int hl  = it / WQ;
        int wg4 = (it - hl * WQ) * 4;
        float a0 = bb, a1 = bb, a2 = bb, a3 = bb;
        #pragma unroll
        for (int z = 0; z < 3; z++)
            #pragma unroll
            for (int y = 0; y < 3; y++) {
                const float* row = &smp[(z * 18 + hl + y) * SW];
                float m1  = row[wg4 + 3];
                float4 v4 = *(const float4*)&row[wg4 + 4];
                float p   = row[wg4 + 8];
                float w0 = wt[(z * 3 + y) * 3 + 0];
                float w1 = wt[(z * 3 + y) * 3 + 1];
                float w2 = wt[(z * 3 + y) * 3 + 2];
                a0 += w0 * m1   + w1 * v4.x + w2 * v4.y;
                a1 += w0 * v4.x + w1 * v4.y + w2 * v4.z;
                a2 += w0 * v4.y + w1 * v4.z + w2 * v4.w;
                a3 += w0 * v4.z + w1 * v4.w + w2 * p;
            }
        float4 o = {leaky(a0), leaky(a1), leaky(a2), leaky(a3)};
        *(float4*)&out[((size_t)(n * C + c) * D + d) * H * W + (h0 + hl) * W + wg4] = o;
    }
}

// ---------------------------------------------------------------------------
// Depthwise 3x3x3, stride 2, pad 1, + leaky. Thread = 4 consecutive wo.
// Per (kz,ky) row: 2x LDG.128 + 1 scalar covers all 9 needed inputs.
// ---------------------------------------------------------------------------
template<int C, int D, int H, int W, int Do, int Ho, int Wo>
__global__ void dw_s2_kernel(const float* __restrict__ in,
                             const float* __restrict__ wgt,
                             const float* __restrict__ bias,
                             float* __restrict__ out)
{
    constexpr int WQ = Wo / 4;
    constexpr int total = NB * C * Do * Ho * WQ;
    int idx = blockIdx.x * blockDim.x + threadIdx.x;
    if (idx >= total) return;
    int t = idx;
    const int q  = t % WQ; t /= WQ;
    const int ho = t % Ho; t /= Ho;
    const int dd = t % Do; t /= Do;
    const int c  = t % C;
    const int n  = t / C;
    const int g  = q * 8;                // 2*wo0, wo0 = 4q

    const float* inb = in + (size_t)(n * C + c) * D * H * W;
    const float* wp  = &wgt[c * 27];
    const float bb = __ldg(&bias[c]);
    float a0 = bb, a1 = bb, a2 = bb, a3 = bb;

    #pragma unroll
    for (int kz = 0; kz < 3; kz++) {
        int zi = 2 * dd - 1 + kz;
        if (zi < 0 || zi >= D) continue;
        #pragma unroll
        for (int ky = 0; ky < 3; ky++) {
            int yi = 2 * ho - 1 + ky;
            if (yi < 0 || yi >= H) continue;
            const float* base = &inb[(size_t)zi * H * W + yi * W];
            float  m1 = (g > 0) ? __ldg(&base[g - 1]) : 0.0f;
            float4 v0 = *(const float4*)&base[g];
            float4 v1 = *(const float4*)&base[g + 4];
            float xv[9] = {m1, v0.x, v0.y, v0.z, v0.w, v1.x, v1.y, v1.z, v1.w};
            float w0 = __ldg(&wp[(kz * 3 + ky) * 3 + 0]);
            float w1 = __ldg(&wp[(kz * 3 + ky) * 3 + 1]);
            float w2 = __ldg(&wp[(kz * 3 + ky) * 3 + 2]);
            a0 += w0 * xv[0] + w1 * xv[1] + w2 * xv[2];
            a1 += w0 * xv[2] + w1 * xv[3] + w2 * xv[4];
            a2 += w0 * xv[4] + w1 * xv[5] + w2 * xv[6];
            a3 += w0 * xv[6] + w1 * xv[7] + w2 * xv[8];
        }
    }
    float4 o = {leaky(a0), leaky(a1), leaky(a2), leaky(a3)};
    size_t obase = ((((size_t)n * C + c) * Do + dd) * Ho + ho) * Wo + q * 4;
    *(float4*)&out[obase] = o;
}

// ---------------------------------------------------------------------------
// Pointwise Cin->Cout + leaky. Thread = 4 contiguous positions x COT-co tile.
// ---------------------------------------------------------------------------
template<int Cin, int COT>
__global__ void pw_kernel(const float* __restrict__ in,
                          const float* __restrict__ wgt,
                          const float* __restrict__ bias,
                          float* __restrict__ out,
                          int Cout, int plane, int nquad)
{
    __shared__ float sw[COT * Cin];
    __shared__ float sb[COT];

    const int co0 = blockIdx.y * COT;
    const int tid = threadIdx.x;

    for (int i = tid; i < COT * Cin; i += blockDim.x) {
        int j  = i / Cin;
        int ci = i - j * Cin;
        sw[i] = wgt[(co0 + j) * Cin + ci];
    }
    if (tid < COT) sb[tid] = bias[co0 + tid];
    __syncthreads();

    const int t = blockIdx.x * blockDim.x + tid;
    if (t >= nquad) return;
    const int s0 = t * 4;
    const int n  = s0 / plane;
    const int p  = s0 - n * plane;

    const float* inb = in + (size_t)n * Cin * plane + p;

    float acc[COT][4];
    #pragma unroll
    for (int j = 0; j < COT; j++) {
        float bv = sb[j];
        acc[j][0] = bv; acc[j][1] = bv; acc[j][2] = bv; acc[j][3] = bv;
    }

    #pragma unroll
    for (int ci = 0; ci < Cin; ci++) {
        float4 x4 = *(const float4*)&inb[(size_t)ci * plane];
        #pragma unroll
        for (int j = 0; j < COT; j++) {
            float wv = sw[j * Cin + ci];
            acc[j][0] += wv * x4.x;
            acc[j][1] += wv * x4.y;
            acc[j][2] += wv * x4.z;
            acc[j][3] += wv * x4.w;
        }
    }

    float* ob = out + (size_t)n * Cout * plane + p;
    #pragma unroll
    for (int j = 0; j < COT; j++) {
        float4 o = {leaky(acc[j][0]), leaky(acc[j][1]),
                    leaky(acc[j][2]), leaky(acc[j][3])};
        *(float4*)&ob[(size_t)(co0 + j) * plane] = o;
    }
}

// ---------------------------------------------------------------------------
extern "C" void kernel_launch(void* const* d_in, const int* in_sizes, int n_in,
                              void* d_out, int out_size)
{
    const float* rgb   = (const float*)d_in[0];
    const float* dep   = (const float*)d_in[1];
    const float* dw1_w = (const float*)d_in[2];
    const float* dw1_b = (const float*)d_in[3];
    const float* pw1_w = (const float*)d_in[4];
    const float* pw1_b = (const float*)d_in[5];
    const float* dw2_w = (const float*)d_in[6];
    const float* dw2_b = (const float*)d_in[7];
    const float* pw2_w = (const float*)d_in[8];
    const float* pw2_b = (const float*)d_in[9];
    const float* dw3_w = (const float*)d_in[10];
    const float* dw3_b = (const float*)d_in[11];
    const float* pw3_w = (const float*)d_in[12];
    const float* pw3_b = (const float*)d_in[13];
    const float* dw4_w = (const float*)d_in[14];
    const float* dw4_b = (const float*)d_in[15];
    const float* pw4_w = (const float*)d_in[16];
    const float* pw4_b = (const float*)d_in[17];
    float* out = (float*)d_out;

    float *bufA = nullptr, *bufB = nullptr;
    cudaGetSymbolAddress((void**)&bufA, g_bufA);
    cudaGetSymbolAddress((void**)&bufB, g_bufB);

    // ---- correlation -> bufA ----
    const int smem_corr = (16 * 192 + 2 * 16 * 212) * 4;   // 39,424 B
    cudaFuncSetAttribute(corr_kernel,
                         cudaFuncAttributeMaxDynamicSharedMemorySize, smem_corr);
    corr_kernel<<<dim3(NH, NP / 2, NB), 128, smem_corr>>>(rgb, dep, bufA);

    // ---- block 1 (stride 1): dw 20ch on (20,64,192), pw 20->20 ----
    dw_s1_kernel<20, 20, 64, 192, 4><<<NB * 20 * 20 * 4, 256>>>(bufA, dw1_w, dw1_b, bufB);
    {
        const int plane = 20 * 64 * 192;
        const int nquad = NB * plane / 4;
        pw_kernel<20, 20><<<dim3((nquad + 255) / 256, 1), 256>>>(bufB, pw1_w, pw1_b, bufA,
                                                                 20, plane, nquad);
    }

    // ---- block 2 (stride 2): dw -> (20,10,32,96), pw 20->40 ----
    {
        const int threads = NB * 20 * 10 * 32 * (96 / 4);
        dw_s2_kernel<20, 20, 64, 192, 10, 32, 96>
            <<<(threads + 255) / 256, 256>>>(bufA, dw2_w, dw2_b, bufB);
        const int plane = 10 * 32 * 96;
        const int nquad = NB * plane / 4;
        pw_kernel<20, 20><<<dim3((nquad + 255) / 256, 2), 256>>>(bufB, pw2_w, pw2_b, bufA,
                                                                 40, plane, nquad);
    }

    // ---- block 3 (stride 1): dw 40ch on (10,32,96), pw 40->40 ----
    dw_s1_kernel<40, 10, 32, 96, 2><<<NB * 40 * 10 * 2, 256>>>(bufA, dw3_w, dw3_b, bufB);
    {
        const int plane = 10 * 32 * 96;
        const int nquad = NB * plane / 4;
        pw_kernel<40, 20><<<dim3((nquad + 255) / 256, 2), 256>>>(bufB, pw3_w, pw3_b, bufA,
                                                                 40, plane, nquad);
    }

    // ---- block 4 (stride 2): dw -> (40,5,16,48), pw 40->80 -> d_out ----
    {
        const int threads = NB * 40 * 5 * 16 * (48 / 4);
        dw_s2_kernel<40, 10, 32, 96, 5, 16, 48>
            <<<(threads + 255) / 256, 256>>>(bufA, dw4_w, dw4_b, bufB);
        const int plane = 5 * 16 * 48;
        const int nquad = NB * plane / 4;
        pw_kernel<40, 20><<<dim3((nquad + 255) / 256, 4), 256>>>(bufB, pw4_w, pw4_b, out,
                                                                 80, plane, nquad);
    }
}